// round 5
// baseline (speedup 1.0000x reference)
#include <cuda_runtime.h>

// FlowNetC correlation on GB300 — round 5: banded tf32 MMA with de-interleaved,
// pre-converted (tf32) smem and conflict-free fragment loads.
//
// out[b, dy*21+dx, y, x] = (1/256) * sum_c in1[b,c,y,x] * in2[b,c, y+2dy-20, x+2dx-20]
//
// Parity de-interleave: x = 2*xh+par; out[xh,dx] = sum_c A[c,xh]*B[c,xh+dx] is a
// banded A^T*B. Block = (dyg of 7 dy, y, b), 14 warps: warp -> (dyl, parity).
// Per warp: 4 m16 tiles x 5 n8 band tiles x 32 k8 steps of mma.m16n8k8.tf32.
//
// R5: producer LDG->cvt.rna.tf32->deint STS (register-prefetch double buffer);
// consumer is pure unit-stride LDS (rows = 8 mod 32 -> zero bank conflicts) + MMA.

#define DD      21
#define HH      96
#define WW      128
#define C_TOT   256
#define CKT     8                  // channels per chunk (= one k8 step)
#define NCH     (C_TOT / CKT)      // 32
#define NTH     448                // 14 warps

// de-interleaved smem layout (units: 32-bit words, tf32 bit patterns)
#define ULEN    104                // B u-row (>=88 used, ==8 mod 32)
#define B_PSTR  (CKT * ULEN)       // 832:  par stride
#define B_DSTR  (2 * B_PSTR)       // 1664: dyl stride
#define B_WORDS (7 * B_DSTR)       // 11648
#define AMLEN   72                 // A m-row (>=64 used, ==8 mod 32)
#define A_PSTR  (CKT * AMLEN)      // 576
#define A_BASE  B_WORDS            // 11648
#define SMEM_WORDS (B_WORDS + 2 * A_PSTR)   // 12800 words = 51200 B

__device__ __forceinline__ unsigned cvt_tf32(float v) {
    unsigned r;
    asm("cvt.rna.tf32.f32 %0, %1;" : "=r"(r) : "f"(v));
    return r;
}
__device__ __forceinline__ void mma_tf32(float (&d)[4],
                                         unsigned a0, unsigned a1,
                                         unsigned a2, unsigned a3,
                                         unsigned b0, unsigned b1) {
    asm volatile(
        "mma.sync.aligned.m16n8k8.row.col.f32.tf32.tf32.f32 "
        "{%0,%1,%2,%3}, {%4,%5,%6,%7}, {%8,%9}, {%0,%1,%2,%3};"
        : "+f"(d[0]), "+f"(d[1]), "+f"(d[2]), "+f"(d[3])
        : "r"(a0), "r"(a1), "r"(a2), "r"(a3), "r"(b0), "r"(b1));
}

extern __shared__ unsigned smw[];   // tf32 bit patterns

__global__ void __launch_bounds__(NTH) corr_mma(
    const float* __restrict__ g_in1,
    const float* __restrict__ g_in2,
    float*       __restrict__ g_out)
{
    const int b    = blockIdx.z;
    const int y    = blockIdx.y;
    const int dyg  = blockIdx.x;      // 0..2
    const int dy0  = dyg * 7;
    const int tid  = threadIdx.x;
    const int lane = tid & 31;
    const int w    = tid >> 5;
    const int dyl  = w >> 1;          // 0..6
    const int par  = w & 1;
    const int g    = lane >> 2;       // 0..7
    const int t    = lane & 3;        // 0..3

    const size_t plane = (size_t)HH * WW;
    const size_t cstep = (size_t)CKT * plane;

    // Zero all smem once: pads + OOB-dy rows stay zero; interiors are
    // rewritten every chunk by the producer.
    for (int i = tid; i < SMEM_WORDS; i += NTH) smw[i] = 0u;

    // ---- producer slot setup: B = 1792 float4/chunk (4/thread), A = 256 (tid<256) ----
    const float* bsrc[4];
    int          bdst[4];     // word offset of even-parity float2 slot
    bool         bok[4];
    #pragma unroll
    for (int q = 0; q < 4; ++q) {
        int idx  = q * NTH + tid;        // 0..1791
        int col4 = idx & 31;
        int c    = (idx >> 5) & 7;
        int dl   = idx >> 8;             // 0..6
        int row2 = y + 2 * (dy0 + dl) - 20;
        bok[q]  = (row2 >= 0) && (row2 < HH);
        bsrc[q] = g_in2 + ((size_t)b * C_TOT + c) * plane
                        + (size_t)(bok[q] ? row2 : 0) * WW + col4 * 4;
        bdst[q] = dl * B_DSTR + c * ULEN + 2 * col4 + 10;   // par1 = +B_PSTR
    }
    const bool   aact = (tid < 256);
    const float* asrc = g_in1 + ((size_t)b * C_TOT + (tid >> 5)) * plane
                              + (size_t)y * WW + (tid & 31) * 4;
    const int    adst = A_BASE + (tid >> 5) * AMLEN + 2 * (tid & 31);  // par1 = +A_PSTR

    float acc[20][4];
    #pragma unroll
    for (int f = 0; f < 20; ++f)
        #pragma unroll
        for (int e = 0; e < 4; ++e) acc[f][e] = 0.0f;

    // ---- prefetch chunk 0 (convert during prefetch) ----
    uint4 pf[4], pa;
    #pragma unroll
    for (int q = 0; q < 4; ++q) {
        float4 v = bok[q] ? *(const float4*)bsrc[q]
                          : make_float4(0.f, 0.f, 0.f, 0.f);
        pf[q] = make_uint4(cvt_tf32(v.x), cvt_tf32(v.y), cvt_tf32(v.z), cvt_tf32(v.w));
        bsrc[q] += cstep;
    }
    if (aact) {
        float4 v = *(const float4*)asrc;
        pa = make_uint4(cvt_tf32(v.x), cvt_tf32(v.y), cvt_tf32(v.z), cvt_tf32(v.w));
        asrc += cstep;
    }

    const unsigned* Bw = smw + dyl * B_DSTR + par * B_PSTR;   // [c][u]
    const unsigned* Aw = smw + A_BASE + par * A_PSTR;          // [c][m]

    for (int k = 0; k < NCH; ++k) {
        __syncthreads();   // previous chunk fully consumed

        // de-interleaved store: float4 cols {4c4..4c4+3} -> even {x,z}, odd {y,w}
        #pragma unroll
        for (int q = 0; q < 4; ++q) {
            *(uint2*)&smw[bdst[q]]          = make_uint2(pf[q].x, pf[q].z);
            *(uint2*)&smw[bdst[q] + B_PSTR] = make_uint2(pf[q].y, pf[q].w);
        }
        if (aact) {
            *(uint2*)&smw[adst]          = make_uint2(pa.x, pa.z);
            *(uint2*)&smw[adst + A_PSTR] = make_uint2(pa.y, pa.w);
        }
        __syncthreads();   // chunk k ready

        // prefetch + convert chunk k+1 (overlapped with compute)
        if (k + 1 < NCH) {
            #pragma unroll
            for (int q = 0; q < 4; ++q) {
                float4 v = bok[q] ? *(const float4*)bsrc[q]
                                  : make_float4(0.f, 0.f, 0.f, 0.f);
                pf[q] = make_uint4(cvt_tf32(v.x), cvt_tf32(v.y),
                                   cvt_tf32(v.z), cvt_tf32(v.w));
                bsrc[q] += cstep;
            }
            if (aact) {
                float4 v = *(const float4*)asrc;
                pa = make_uint4(cvt_tf32(v.x), cvt_tf32(v.y),
                                cvt_tf32(v.z), cvt_tf32(v.w));
                asrc += cstep;
            }
        }

        // ---- compute chunk k: conflict-free unit-stride LDS + 20 MMA ----
        unsigned a[4][4];
        #pragma unroll
        for (int mt = 0; mt < 4; ++mt) {
            int m0 = 16 * mt + g;
            a[mt][0] = Aw[t * AMLEN + m0];
            a[mt][1] = Aw[t * AMLEN + m0 + 8];
            a[mt][2] = Aw[(t + 4) * AMLEN + m0];
            a[mt][3] = Aw[(t + 4) * AMLEN + m0 + 8];
        }
        #pragma unroll
        for (int j = 0; j < 11; ++j) {
            int u = 8 * j + g;
            unsigned b0 = Bw[t * ULEN + u];
            unsigned b1 = Bw[(t + 4) * ULEN + u];
            #pragma unroll
            for (int mt = 0; mt < 4; ++mt)
                if (2 * mt <= j && j <= 2 * mt + 4)
                    mma_tf32(acc[mt * 5 + (j - 2 * mt)],
                             a[mt][0], a[mt][1], a[mt][2], a[mt][3], b0, b1);
        }
    }

    // ---- epilogue: band-extract + scatter stores (proven in R4) ----
    const float scale = 1.0f / 256.0f;
    const int   dy    = dy0 + dyl;
    float* ob = g_out + ((size_t)(b * (DD * DD) + dy * DD)) * plane
                      + (size_t)y * WW + par;
    #pragma unroll
    for (int mt = 0; mt < 4; ++mt) {
        #pragma unroll
        for (int i = 0; i < 5; ++i) {
            const int u0 = 8 * (2 * mt + i);
            const float* f = acc[mt * 5 + i];
            #pragma unroll
            for (int e = 0; e < 4; ++e) {
                int r   = (e >= 2) ? (g + 8) : g;
                int col = 2 * t + (e & 1);
                int xh  = 16 * mt + r;
                int dx  = u0 + col - xh;
                if (dx >= 0 && dx < DD)
                    ob[(size_t)dx * plane + 2 * xh] = f[e] * scale;
            }
        }
    }
}

extern "C" void kernel_launch(void* const* d_in, const int* in_sizes, int n_in,
                              void* d_out, int out_size)
{
    (void)in_sizes; (void)n_in; (void)out_size;
    const float* in1 = (const float*)d_in[0];
    const float* in2 = (const float*)d_in[1];
    float*       out = (float*)d_out;

    cudaFuncSetAttribute(corr_mma, cudaFuncAttributeMaxDynamicSharedMemorySize,
                         SMEM_WORDS * 4);

    dim3 grid(3, HH, 8);     // (dy-group, y, b) -> 2304 blocks
    dim3 block(NTH);         // 448 = 14 warps
    corr_mma<<<grid, block, SMEM_WORDS * 4>>>(in1, in2, out);
}

// round 6
// speedup vs baseline: 1.0087x; 1.0087x over previous
#include <cuda_runtime.h>

// FlowNetC correlation on GB300 — round 6: banded tf32 MMA, de-interleaved
// pre-converted smem, DOUBLE-BUFFERED with a single __syncthreads per chunk.
//
// out[b, dy*21+dx, y, x] = (1/256) * sum_c in1[b,c,y,x] * in2[b,c, y+2dy-20, x+2dx-20]
//
// Parity de-interleave: x = 2*xh+par; out[xh,dx] = sum_c A[c,xh]*B[c,xh+dx] is a
// banded A^T*B. Block = (dyg of 7 dy, y, b), 14 warps: warp -> (dyl, parity).
// Per warp: 4 m16 tiles x 5 n8 band tiles x 32 k8 steps of mma.m16n8k8.tf32.
//
// R6 pipeline (1 barrier/chunk):
//   iter k: store pf(k) -> buf[k&1]; __syncthreads; LDG pf(k+1); compute buf[k&1]
// Safety: warp stores k+1 only after its compute of k (program order); barrier of
// iter k+1 therefore orders ALL compute of k before iter k+2 overwrites buf[k&1].

#define DD      21
#define HH      96
#define WW      128
#define C_TOT   256
#define CKT     8                  // channels per chunk (= one k8 step)
#define NCH     (C_TOT / CKT)      // 32
#define NTH     448                // 14 warps

// de-interleaved smem layout (units: 32-bit words, tf32 bit patterns)
#define ULEN    104                // B u-row (>=88 used, ==8 mod 32)
#define B_PSTR  (CKT * ULEN)       // 832:  par stride
#define B_DSTR  (2 * B_PSTR)       // 1664: dyl stride
#define B_WORDS (7 * B_DSTR)       // 11648
#define AMLEN   72                 // A m-row (>=64 used, ==8 mod 32)
#define A_PSTR  (CKT * AMLEN)      // 576
#define A_BASE  B_WORDS            // 11648
#define STAGE   (B_WORDS + 2 * A_PSTR)     // 12800 words per stage
#define SMEM_WORDS (2 * STAGE)             // 25600 words = 102400 B

__device__ __forceinline__ unsigned cvt_tf32(float v) {
    unsigned r;
    asm("cvt.rna.tf32.f32 %0, %1;" : "=r"(r) : "f"(v));
    return r;
}
__device__ __forceinline__ void mma_tf32(float (&d)[4],
                                         unsigned a0, unsigned a1,
                                         unsigned a2, unsigned a3,
                                         unsigned b0, unsigned b1) {
    asm volatile(
        "mma.sync.aligned.m16n8k8.row.col.f32.tf32.tf32.f32 "
        "{%0,%1,%2,%3}, {%4,%5,%6,%7}, {%8,%9}, {%0,%1,%2,%3};"
        : "+f"(d[0]), "+f"(d[1]), "+f"(d[2]), "+f"(d[3])
        : "r"(a0), "r"(a1), "r"(a2), "r"(a3), "r"(b0), "r"(b1));
}

extern __shared__ unsigned smw[];   // tf32 bit patterns

__global__ void __launch_bounds__(NTH) corr_mma(
    const float* __restrict__ g_in1,
    const float* __restrict__ g_in2,
    float*       __restrict__ g_out)
{
    const int b    = blockIdx.z;
    const int y    = blockIdx.y;
    const int dyg  = blockIdx.x;      // 0..2
    const int dy0  = dyg * 7;
    const int tid  = threadIdx.x;
    const int lane = tid & 31;
    const int w    = tid >> 5;
    const int dyl  = w >> 1;          // 0..6
    const int par  = w & 1;
    const int g    = lane >> 2;       // 0..7
    const int t    = lane & 3;        // 0..3

    const size_t plane = (size_t)HH * WW;
    const size_t cstep = (size_t)CKT * plane;

    // Zero both stages once: pads + OOB-dy rows stay zero; interiors are
    // rewritten every chunk by the producer.
    for (int i = tid; i < SMEM_WORDS; i += NTH) smw[i] = 0u;

    // ---- producer slot setup: B = 1792 float4/chunk (4/thread), A = 256 (tid<256) ----
    const float* bsrc[4];
    int          bdst[4];     // word offset of even-parity float2 slot (stage 0)
    bool         bok[4];
    #pragma unroll
    for (int q = 0; q < 4; ++q) {
        int idx  = q * NTH + tid;        // 0..1791
        int col4 = idx & 31;
        int c    = (idx >> 5) & 7;
        int dl   = idx >> 8;             // 0..6
        int row2 = y + 2 * (dy0 + dl) - 20;
        bok[q]  = (row2 >= 0) && (row2 < HH);
        bsrc[q] = g_in2 + ((size_t)b * C_TOT + c) * plane
                        + (size_t)(bok[q] ? row2 : 0) * WW + col4 * 4;
        bdst[q] = dl * B_DSTR + c * ULEN + 2 * col4 + 10;   // par1 = +B_PSTR
    }
    const bool   aact = (tid < 256);
    const float* asrc = g_in1 + ((size_t)b * C_TOT + (tid >> 5)) * plane
                              + (size_t)y * WW + (tid & 31) * 4;
    const int    adst = A_BASE + (tid >> 5) * AMLEN + 2 * (tid & 31);  // par1 = +A_PSTR

    float acc[20][4];
    #pragma unroll
    for (int f = 0; f < 20; ++f)
        #pragma unroll
        for (int e = 0; e < 4; ++e) acc[f][e] = 0.0f;

    // ---- prefetch chunk 0 (convert during prefetch) ----
    uint4 pf[4], pa;
    #pragma unroll
    for (int q = 0; q < 4; ++q) {
        float4 v = bok[q] ? *(const float4*)bsrc[q]
                          : make_float4(0.f, 0.f, 0.f, 0.f);
        pf[q] = make_uint4(cvt_tf32(v.x), cvt_tf32(v.y), cvt_tf32(v.z), cvt_tf32(v.w));
        bsrc[q] += cstep;
    }
    if (aact) {
        float4 v = *(const float4*)asrc;
        pa = make_uint4(cvt_tf32(v.x), cvt_tf32(v.y), cvt_tf32(v.z), cvt_tf32(v.w));
        asrc += cstep;
    }

    const unsigned* Bw0 = smw + dyl * B_DSTR + par * B_PSTR;   // [c][u], stage 0
    const unsigned* Aw0 = smw + A_BASE + par * A_PSTR;         // [c][m], stage 0

    __syncthreads();   // zeroing complete before first stores

    for (int k = 0; k < NCH; ++k) {
        const int so = (k & 1) * STAGE;

        // store chunk k into stage (k&1): de-interleave {x,z} even / {y,w} odd
        #pragma unroll
        for (int q = 0; q < 4; ++q) {
            *(uint2*)&smw[so + bdst[q]]          = make_uint2(pf[q].x, pf[q].z);
            *(uint2*)&smw[so + bdst[q] + B_PSTR] = make_uint2(pf[q].y, pf[q].w);
        }
        if (aact) {
            *(uint2*)&smw[so + adst]          = make_uint2(pa.x, pa.z);
            *(uint2*)&smw[so + adst + A_PSTR] = make_uint2(pa.y, pa.w);
        }
        __syncthreads();   // chunk k visible; also orders compute k-1 vs stores k+1

        // prefetch + convert chunk k+1 (overlapped with compute below)
        if (k + 1 < NCH) {
            #pragma unroll
            for (int q = 0; q < 4; ++q) {
                float4 v = bok[q] ? *(const float4*)bsrc[q]
                                  : make_float4(0.f, 0.f, 0.f, 0.f);
                pf[q] = make_uint4(cvt_tf32(v.x), cvt_tf32(v.y),
                                   cvt_tf32(v.z), cvt_tf32(v.w));
                bsrc[q] += cstep;
            }
            if (aact) {
                float4 v = *(const float4*)asrc;
                pa = make_uint4(cvt_tf32(v.x), cvt_tf32(v.y),
                                cvt_tf32(v.z), cvt_tf32(v.w));
                asrc += cstep;
            }
        }

        // ---- compute chunk k: conflict-free unit-stride LDS + 20 MMA ----
        const unsigned* Bw = Bw0 + so;
        const unsigned* Aw = Aw0 + so;
        unsigned a[4][4];
        #pragma unroll
        for (int mt = 0; mt < 4; ++mt) {
            int m0 = 16 * mt + g;
            a[mt][0] = Aw[t * AMLEN + m0];
            a[mt][1] = Aw[t * AMLEN + m0 + 8];
            a[mt][2] = Aw[(t + 4) * AMLEN + m0];
            a[mt][3] = Aw[(t + 4) * AMLEN + m0 + 8];
        }
        #pragma unroll
        for (int j = 0; j < 11; ++j) {
            int u = 8 * j + g;
            unsigned b0 = Bw[t * ULEN + u];
            unsigned b1 = Bw[(t + 4) * ULEN + u];
            #pragma unroll
            for (int mt = 0; mt < 4; ++mt)
                if (2 * mt <= j && j <= 2 * mt + 4)
                    mma_tf32(acc[mt * 5 + (j - 2 * mt)],
                             a[mt][0], a[mt][1], a[mt][2], a[mt][3], b0, b1);
        }
        // no second barrier: next iter stores to the other stage
    }

    // ---- epilogue: band-extract + scatter stores ----
    const float scale = 1.0f / 256.0f;
    const int   dy    = dy0 + dyl;
    float* ob = g_out + ((size_t)(b * (DD * DD) + dy * DD)) * plane
                      + (size_t)y * WW + par;
    #pragma unroll
    for (int mt = 0; mt < 4; ++mt) {
        #pragma unroll
        for (int i = 0; i < 5; ++i) {
            const int u0 = 8 * (2 * mt + i);
            const float* f = acc[mt * 5 + i];
            #pragma unroll
            for (int e = 0; e < 4; ++e) {
                int r   = (e >= 2) ? (g + 8) : g;
                int col = 2 * t + (e & 1);
                int xh  = 16 * mt + r;
                int dx  = u0 + col - xh;
                if (dx >= 0 && dx < DD)
                    ob[(size_t)dx * plane + 2 * xh] = f[e] * scale;
            }
        }
    }
}

extern "C" void kernel_launch(void* const* d_in, const int* in_sizes, int n_in,
                              void* d_out, int out_size)
{
    (void)in_sizes; (void)n_in; (void)out_size;
    const float* in1 = (const float*)d_in[0];
    const float* in2 = (const float*)d_in[1];
    float*       out = (float*)d_out;

    cudaFuncSetAttribute(corr_mma, cudaFuncAttributeMaxDynamicSharedMemorySize,
                         SMEM_WORDS * 4);

    dim3 grid(3, HH, 8);     // (dy-group, y, b) -> 2304 blocks
    dim3 block(NTH);         // 448 = 14 warps
    corr_mma<<<grid, block, SMEM_WORDS * 4>>>(in1, in2, out);
}

// round 7
// speedup vs baseline: 1.2139x; 1.2034x over previous
#include <cuda_runtime.h>

// FlowNetC correlation on GB300 — round 7: banded tf32 MMA, spill-free config.
//
// out[b, dy*21+dx, y, x] = (1/256) * sum_c in1[b,c,y,x] * in2[b,c, y+2dy-20, x+2dx-20]
//
// R4-R6 all pinned at ~730us with regs=128 (= 65536/448 cap) vs ~155-reg working
// set -> ptxas spilled ~25 regs into the inner loop. R7 shrinks the block to
// 6 warps (3 dy x 2 parity, 192 threads), __launch_bounds__(192,2) -> 168-reg
// budget, zero spills, 2 blocks/SM. Compute core unchanged (R5: de-interleaved
// pre-converted tf32 smem, conflict-free unit-stride LDS, 20 band MMAs/chunk,
// double-buffered single-barrier pipeline).

#define DD      21
#define HH      96
#define WW      128
#define C_TOT   256
#define CKT     8                  // channels per chunk (= one k8 step)
#define NCH     (C_TOT / CKT)      // 32
#define NDY     3                  // dy per block
#define NTH     192                // 6 warps = 3 dy x 2 parity

// de-interleaved smem layout (units: 32-bit words, tf32 bit patterns)
#define ULEN    104                // B u-row (>=88 used, ==8 mod 32)
#define B_PSTR  (CKT * ULEN)       // 832:  par stride
#define B_DSTR  (2 * B_PSTR)       // 1664: dyl stride
#define B_WORDS (NDY * B_DSTR)     // 4992
#define AMLEN   72                 // A m-row (>=64 used, ==8 mod 32)
#define A_PSTR  (CKT * AMLEN)      // 576
#define A_BASE  B_WORDS            // 4992
#define STAGE   (B_WORDS + 2 * A_PSTR)     // 6144 words per stage
#define SMEM_WORDS (2 * STAGE)             // 12288 words = 49152 B

__device__ __forceinline__ unsigned cvt_tf32(float v) {
    unsigned r;
    asm("cvt.rna.tf32.f32 %0, %1;" : "=r"(r) : "f"(v));
    return r;
}
__device__ __forceinline__ void mma_tf32(float (&d)[4],
                                         unsigned a0, unsigned a1,
                                         unsigned a2, unsigned a3,
                                         unsigned b0, unsigned b1) {
    asm volatile(
        "mma.sync.aligned.m16n8k8.row.col.f32.tf32.tf32.f32 "
        "{%0,%1,%2,%3}, {%4,%5,%6,%7}, {%8,%9}, {%0,%1,%2,%3};"
        : "+f"(d[0]), "+f"(d[1]), "+f"(d[2]), "+f"(d[3])
        : "r"(a0), "r"(a1), "r"(a2), "r"(a3), "r"(b0), "r"(b1));
}

extern __shared__ unsigned smw[];   // tf32 bit patterns

__global__ void __launch_bounds__(NTH, 2) corr_mma(
    const float* __restrict__ g_in1,
    const float* __restrict__ g_in2,
    float*       __restrict__ g_out)
{
    const int b    = blockIdx.z;
    const int y    = blockIdx.y;
    const int dyg  = blockIdx.x;      // 0..6
    const int dy0  = dyg * NDY;
    const int tid  = threadIdx.x;
    const int lane = tid & 31;
    const int w    = tid >> 5;        // 0..5
    const int dyl  = w >> 1;          // 0..2
    const int par  = w & 1;
    const int g    = lane >> 2;       // 0..7
    const int t    = lane & 3;        // 0..3

    const size_t plane = (size_t)HH * WW;
    const size_t cstep = (size_t)CKT * plane;

    // Zero both stages once: pads + OOB-dy rows stay zero.
    for (int i = tid; i < SMEM_WORDS; i += NTH) smw[i] = 0u;

    // ---- producer slots: B = 768 float4/chunk (4/thread exactly) ----
    const float* bsrc[4];
    int          bdst[4];     // word offset of even-parity float2 slot (stage 0)
    bool         bok[4];
    #pragma unroll
    for (int q = 0; q < 4; ++q) {
        int idx  = q * NTH + tid;        // 0..767
        int col4 = idx & 31;
        int c    = (idx >> 5) & 7;
        int dl   = idx >> 8;             // 0..2
        int row2 = y + 2 * (dy0 + dl) - 20;
        bok[q]  = (row2 >= 0) && (row2 < HH);
        bsrc[q] = g_in2 + ((size_t)b * C_TOT + c) * plane
                        + (size_t)(bok[q] ? row2 : 0) * WW + col4 * 4;
        bdst[q] = dl * B_DSTR + c * ULEN + 2 * col4 + 10;   // par1 = +B_PSTR
    }
    // A = 256 float4/chunk: slot0 = all 192 threads (c 0..5), slot1 = tid<64 (c 6..7)
    const bool   a1act = (tid < 64);
    const float* asrc0 = g_in1 + ((size_t)b * C_TOT + (tid >> 5)) * plane
                               + (size_t)y * WW + (tid & 31) * 4;
    const float* asrc1 = g_in1 + ((size_t)b * C_TOT + 6 + (tid >> 5)) * plane
                               + (size_t)y * WW + (tid & 31) * 4;
    const int    adst0 = A_BASE + (tid >> 5) * AMLEN + 2 * (tid & 31);
    const int    adst1 = A_BASE + (6 + (tid >> 5)) * AMLEN + 2 * (tid & 31);

    float acc[20][4];
    #pragma unroll
    for (int f = 0; f < 20; ++f)
        #pragma unroll
        for (int e = 0; e < 4; ++e) acc[f][e] = 0.0f;

    // ---- prefetch chunk 0 (convert during prefetch) ----
    uint4 pf[4], pa0, pa1;
    #pragma unroll
    for (int q = 0; q < 4; ++q) {
        float4 v = bok[q] ? *(const float4*)bsrc[q]
                          : make_float4(0.f, 0.f, 0.f, 0.f);
        pf[q] = make_uint4(cvt_tf32(v.x), cvt_tf32(v.y), cvt_tf32(v.z), cvt_tf32(v.w));
        bsrc[q] += cstep;
    }
    {
        float4 v = *(const float4*)asrc0;
        pa0 = make_uint4(cvt_tf32(v.x), cvt_tf32(v.y), cvt_tf32(v.z), cvt_tf32(v.w));
        asrc0 += cstep;
    }
    if (a1act) {
        float4 v = *(const float4*)asrc1;
        pa1 = make_uint4(cvt_tf32(v.x), cvt_tf32(v.y), cvt_tf32(v.z), cvt_tf32(v.w));
        asrc1 += cstep;
    }

    const unsigned* Bw0 = smw + dyl * B_DSTR + par * B_PSTR;   // [c][u], stage 0
    const unsigned* Aw0 = smw + A_BASE + par * A_PSTR;         // [c][m], stage 0

    __syncthreads();   // zeroing complete before first stores

    for (int k = 0; k < NCH; ++k) {
        const int so = (k & 1) * STAGE;

        // store chunk k into stage (k&1): de-interleave {x,z} even / {y,w} odd
        #pragma unroll
        for (int q = 0; q < 4; ++q) {
            *(uint2*)&smw[so + bdst[q]]          = make_uint2(pf[q].x, pf[q].z);
            *(uint2*)&smw[so + bdst[q] + B_PSTR] = make_uint2(pf[q].y, pf[q].w);
        }
        *(uint2*)&smw[so + adst0]          = make_uint2(pa0.x, pa0.z);
        *(uint2*)&smw[so + adst0 + A_PSTR] = make_uint2(pa0.y, pa0.w);
        if (a1act) {
            *(uint2*)&smw[so + adst1]          = make_uint2(pa1.x, pa1.z);
            *(uint2*)&smw[so + adst1 + A_PSTR] = make_uint2(pa1.y, pa1.w);
        }
        __syncthreads();   // chunk k visible; also orders compute k-1 vs stores k+1

        // prefetch + convert chunk k+1 (overlapped with compute below)
        if (k + 1 < NCH) {
            #pragma unroll
            for (int q = 0; q < 4; ++q) {
                float4 v = bok[q] ? *(const float4*)bsrc[q]
                                  : make_float4(0.f, 0.f, 0.f, 0.f);
                pf[q] = make_uint4(cvt_tf32(v.x), cvt_tf32(v.y),
                                   cvt_tf32(v.z), cvt_tf32(v.w));
                bsrc[q] += cstep;
            }
            {
                float4 v = *(const float4*)asrc0;
                pa0 = make_uint4(cvt_tf32(v.x), cvt_tf32(v.y),
                                 cvt_tf32(v.z), cvt_tf32(v.w));
                asrc0 += cstep;
            }
            if (a1act) {
                float4 v = *(const float4*)asrc1;
                pa1 = make_uint4(cvt_tf32(v.x), cvt_tf32(v.y),
                                 cvt_tf32(v.z), cvt_tf32(v.w));
                asrc1 += cstep;
            }
        }

        // ---- compute chunk k: conflict-free unit-stride LDS + 20 MMA ----
        const unsigned* Bw = Bw0 + so;
        const unsigned* Aw = Aw0 + so;
        unsigned a[4][4];
        #pragma unroll
        for (int mt = 0; mt < 4; ++mt) {
            int m0 = 16 * mt + g;
            a[mt][0] = Aw[t * AMLEN + m0];
            a[mt][1] = Aw[t * AMLEN + m0 + 8];
            a[mt][2] = Aw[(t + 4) * AMLEN + m0];
            a[mt][3] = Aw[(t + 4) * AMLEN + m0 + 8];
        }
        #pragma unroll
        for (int j = 0; j < 11; ++j) {
            int u = 8 * j + g;
            unsigned b0 = Bw[t * ULEN + u];
            unsigned b1 = Bw[(t + 4) * ULEN + u];
            #pragma unroll
            for (int mt = 0; mt < 4; ++mt)
                if (2 * mt <= j && j <= 2 * mt + 4)
                    mma_tf32(acc[mt * 5 + (j - 2 * mt)],
                             a[mt][0], a[mt][1], a[mt][2], a[mt][3], b0, b1);
        }
        // no second barrier: next iter stores to the other stage
    }

    // ---- epilogue: band-extract + scatter stores ----
    const float scale = 1.0f / 256.0f;
    const int   dy    = dy0 + dyl;
    float* ob = g_out + ((size_t)(b * (DD * DD) + dy * DD)) * plane
                      + (size_t)y * WW + par;
    #pragma unroll
    for (int mt = 0; mt < 4; ++mt) {
        #pragma unroll
        for (int i = 0; i < 5; ++i) {
            const int u0 = 8 * (2 * mt + i);
            const float* f = acc[mt * 5 + i];
            #pragma unroll
            for (int e = 0; e < 4; ++e) {
                int r   = (e >= 2) ? (g + 8) : g;
                int col = 2 * t + (e & 1);
                int xh  = 16 * mt + r;
                int dx  = u0 + col - xh;
                if (dx >= 0 && dx < DD)
                    ob[(size_t)dx * plane + 2 * xh] = f[e] * scale;
            }
        }
    }
}

extern "C" void kernel_launch(void* const* d_in, const int* in_sizes, int n_in,
                              void* d_out, int out_size)
{
    (void)in_sizes; (void)n_in; (void)out_size;
    const float* in1 = (const float*)d_in[0];
    const float* in2 = (const float*)d_in[1];
    float*       out = (float*)d_out;

    cudaFuncSetAttribute(corr_mma, cudaFuncAttributeMaxDynamicSharedMemorySize,
                         SMEM_WORDS * 4);

    dim3 grid(7, HH, 8);     // (dy-group of 3, y, b) -> 5376 blocks
    dim3 block(NTH);         // 192 = 6 warps
    corr_mma<<<grid, block, SMEM_WORDS * 4>>>(in1, in2, out);
}